// round 7
// baseline (speedup 1.0000x reference)
#include <cuda_runtime.h>
#include <stdint.h>

// Problem shape (fixed by the dataset): B=1, N=100000, E=3200000, H=8, D=64
#define NN 100000
#define HH 8
#define DD 64
#define EE 3200000
#define TOT (EE*HH)          // 25,600,000 outputs
#define NWORDS (TOT/32)      // 800,000 packed mask words
#define WSPLIT 480000        // words produced by F1 (rest by F2)

#define GRID1 1184           // 8 CTAs/SM * 148 SM
#define GW    (GRID1*8)      // global warps in persistent kernels

// Scratch (static device arrays). 16B-aligned for vec I/O.
__device__ __align__(16) float    g_a_self[NN*HH];
__device__ __align__(16) float    g_a_adjc[NN*HH];
__device__ __align__(16) unsigned g_M[NN*HH];     // order-encoded per-(target,head) max
__device__ __align__(16) unsigned g_mask[NWORDS]; // packed keep bits

// ---------------------------------------------------------------------------
// Threefry-2x32 (20 rounds), key=(0,42), ctr=(0,j), JAX partitionable:
//   bits(j) = x0 ^ x1 ;  keep(j) = bit31 == 0.
// Adds forced onto the IMAD (fma) pipe via mad.lo.u32 with an opaque 'one' so
// the alu pipe carries only the mandatory SHF+LOP3.
// ---------------------------------------------------------------------------
__device__ __forceinline__ unsigned addm(unsigned a, unsigned one, unsigned b) {
  unsigned d;
  asm("mad.lo.u32 %0, %1, %2, %3;" : "=r"(d) : "r"(a), "r"(one), "r"(b));
  return d;
}
__device__ __forceinline__ unsigned tf_xor(unsigned j, unsigned one) {
  const unsigned K1  = 42u;
  const unsigned KS2 = 0x1BD11BDAu ^ 42u;
  unsigned x0 = 0u;                 // c0(=0) + ks0(=0)
  unsigned x1 = addm(j, one, K1);   // c1 + ks1
#define TF_R(r) { x0 = addm(x1, one, x0); x1 = __funnelshift_l(x1, x1, (r)); x1 ^= x0; }
  TF_R(13) TF_R(15) TF_R(26) TF_R(6)
  x0 = addm(one, K1, x0);   x1 = addm(one, KS2 + 1u, x1);
  TF_R(17) TF_R(29) TF_R(16) TF_R(24)
  x0 = addm(one, KS2, x0);  x1 = addm(one, 2u, x1);
  TF_R(13) TF_R(15) TF_R(26) TF_R(6)
  /* ks0 = 0 */             x1 = addm(one, K1 + 3u, x1);
  TF_R(17) TF_R(29) TF_R(16) TF_R(24)
  x0 = addm(one, K1, x0);   x1 = addm(one, KS2 + 4u, x1);
  TF_R(13) TF_R(15) TF_R(26) TF_R(6)
  x0 = addm(one, KS2, x0);  x1 = addm(one, 5u, x1);
#undef TF_R
  return x0 ^ x1;
}

// Mask words [w0, w1): each warp builds one 32-bit word per iteration via ballot.
__device__ __forceinline__ void gen_mask(unsigned w0, unsigned w1,
                                         unsigned gwarp, unsigned lane,
                                         unsigned one) {
  for (unsigned w = w0 + gwarp; w < w1; w += GW) {
    unsigned j = w * 32u + lane;
    unsigned bits = tf_xor(j, one);
    unsigned word = __ballot_sync(0xFFFFFFFFu, (bits & 0x80000000u) == 0u);
    if (lane == 0) g_mask[w] = word;
  }
}

// Order-preserving float<->uint encoding for atomicMax
__device__ __forceinline__ unsigned enc_f(float f) {
  unsigned u = __float_as_uint(f);
  return (u & 0x80000000u) ? ~u : (u | 0x80000000u);
}
__device__ __forceinline__ float dec_f(unsigned k) {
  unsigned u = (k & 0x80000000u) ? (k ^ 0x80000000u) : ~k;
  return __uint_as_float(u);
}

// ---------------------------------------------------------------------------
// F1: dots (einsum 'nhd,dh->nh') + g_M init + mask words [0, WSPLIT).
// One warp per head, 4-node unroll (MLP=4), persistent grid (64 warps/SM).
// ---------------------------------------------------------------------------
#define DOTS_UN 4
__global__ void k_dots_mask(const float* __restrict__ X,
                            const float* __restrict__ Ws,
                            const float* __restrict__ Wa,
                            unsigned one) {
  int w = threadIdx.x >> 5;   // head
  int l = threadIdx.x & 31;
  float ws0 = Ws[(2*l    ) * HH + w];
  float ws1 = Ws[(2*l + 1) * HH + w];
  float wa0 = Wa[(2*l    ) * HH + w];
  float wa1 = Wa[(2*l + 1) * HH + w];

  for (int n0 = blockIdx.x * DOTS_UN; n0 < NN; n0 += GRID1 * DOTS_UN) {
    float2 x[DOTS_UN];
    int nv = (n0 + DOTS_UN <= NN) ? DOTS_UN : (NN - n0);
#pragma unroll
    for (int u = 0; u < DOTS_UN; u++)
      if (u < nv)
        x[u] = *reinterpret_cast<const float2*>(
            X + ((size_t)(n0 + u) * HH + w) * DD + 2*l);
    float ds[DOTS_UN], da[DOTS_UN];
#pragma unroll
    for (int u = 0; u < DOTS_UN; u++)
      if (u < nv) {
        ds[u] = x[u].x * ws0 + x[u].y * ws1;
        da[u] = x[u].x * wa0 + x[u].y * wa1;
      }
#pragma unroll
    for (int o = 16; o; o >>= 1)
#pragma unroll
      for (int u = 0; u < DOTS_UN; u++)
        if (u < nv) {
          ds[u] += __shfl_down_sync(0xFFFFFFFFu, ds[u], o);
          da[u] += __shfl_down_sync(0xFFFFFFFFu, da[u], o);
        }
    if (l == 0)
#pragma unroll
      for (int u = 0; u < DOTS_UN; u++)
        if (u < nv) {
          g_a_self[(n0 + u)*HH + w] = ds[u];
          g_a_adjc[(n0 + u)*HH + w] = da[u];
        }
    if (w == 0 && l < 8 * DOTS_UN) {       // fold g_M zero-init
      int u = l >> 3;
      if (u < nv) g_M[(n0 + u)*8 + (l & 7)] = 0u;
    }
  }

  unsigned gwarp = (blockIdx.x * blockDim.x + threadIdx.x) >> 5;
  gen_mask(0u, (unsigned)WSPLIT, gwarp, (unsigned)l, one);
}

// ---------------------------------------------------------------------------
// F2: segment max (filtered atomics, one edge per iteration per thread)
//     + mask words [WSPLIT, NWORDS).
// ---------------------------------------------------------------------------
__global__ void k_edge_max_mask(const int* __restrict__ targets,
                                const int* __restrict__ sources,
                                unsigned one) {
  for (int e = blockIdx.x * blockDim.x + threadIdx.x; e < EE;
       e += GRID1 * 256) {
    int t = targets[e];
    int s = sources[e];
    const float4 a0 = *reinterpret_cast<const float4*>(g_a_adjc + s*8);
    const float4 a1 = *reinterpret_cast<const float4*>(g_a_adjc + s*8 + 4);
    const uint4  m0 = *reinterpret_cast<const uint4 *>(g_M + t*8);
    const uint4  m1 = *reinterpret_cast<const uint4 *>(g_M + t*8 + 4);
    unsigned v;
    v = enc_f(a0.x); if (v > m0.x) atomicMax(&g_M[t*8 + 0], v);
    v = enc_f(a0.y); if (v > m0.y) atomicMax(&g_M[t*8 + 1], v);
    v = enc_f(a0.z); if (v > m0.z) atomicMax(&g_M[t*8 + 2], v);
    v = enc_f(a0.w); if (v > m0.w) atomicMax(&g_M[t*8 + 3], v);
    v = enc_f(a1.x); if (v > m1.x) atomicMax(&g_M[t*8 + 4], v);
    v = enc_f(a1.y); if (v > m1.y) atomicMax(&g_M[t*8 + 5], v);
    v = enc_f(a1.z); if (v > m1.z) atomicMax(&g_M[t*8 + 6], v);
    v = enc_f(a1.w); if (v > m1.w) atomicMax(&g_M[t*8 + 7], v);
  }
  unsigned gwarp = (blockIdx.x * blockDim.x + threadIdx.x) >> 5;
  gen_mask((unsigned)WSPLIT, (unsigned)NWORDS, gwarp,
           (unsigned)(threadIdx.x & 31), one);
}

// ---------------------------------------------------------------------------
// K3: out[j] = keepbit(j) ? 2*exp(e - m) : 0
//   e = leaky(a_self[t]+a_adjc[s]),  m = leaky(a_self[t]+max),  m2+eps == 1.0f
// 4 outputs per thread; mask read from packed words (memory-bound kernel).
// ---------------------------------------------------------------------------
__device__ __forceinline__ float edge_val(float a_s, float a_a, unsigned menc,
                                          unsigned keep) {
  float x  = a_s + a_a;
  float e  = (x  >= 0.0f) ? x  : 0.2f * x;
  float mx = a_s + dec_f(menc);
  float m  = (mx >= 0.0f) ? mx : 0.2f * mx;
  float v  = __expf(e - m) * 2.0f;
  return keep ? v : 0.0f;
}

__global__ void k_out(const int* __restrict__ targets,
                      const int* __restrict__ sources,
                      float* __restrict__ out) {
  unsigned tI = blockIdx.x * blockDim.x + threadIdx.x;  // 0 .. TOT/4-1
  if (tI >= (unsigned)(TOT/4)) return;
  unsigned j0 = 4u * tI;

  unsigned word = g_mask[j0 >> 5];
  unsigned b = word >> (j0 & 31u);

  int e = (int)(j0 >> 3);
  int h = (int)(j0 & 7u);        // 0 or 4
  int t = targets[e];
  int s = sources[e];
  float4 as = *reinterpret_cast<const float4*>(g_a_self + t*8 + h);
  float4 aa = *reinterpret_cast<const float4*>(g_a_adjc + s*8 + h);
  uint4  me = *reinterpret_cast<const uint4 *>(g_M      + t*8 + h);

  float4 o;
  o.x = edge_val(as.x, aa.x, me.x,  b        & 1u);
  o.y = edge_val(as.y, aa.y, me.y, (b >> 1u) & 1u);
  o.z = edge_val(as.z, aa.z, me.z, (b >> 2u) & 1u);
  o.w = edge_val(as.w, aa.w, me.w, (b >> 3u) & 1u);
  *reinterpret_cast<float4*>(out + j0) = o;
}

// ---------------------------------------------------------------------------
extern "C" void kernel_launch(void* const* d_in, const int* in_sizes, int n_in,
                              void* d_out, int out_size) {
  const float* X  = (const float*)d_in[0];
  const float* Ws = (const float*)d_in[1];
  const float* Wa = (const float*)d_in[2];
  // input order: X, Wself, Wadjc, [N scalar], targets, sources, degree
  int ti = (n_in >= 6 && in_sizes[3] == 1) ? 4 : 3;
  const int* targets = (const int*)d_in[ti];
  const int* sources = (const int*)d_in[ti + 1];
  float* out = (float*)d_out;

  k_dots_mask    <<<GRID1, 256>>>(X, Ws, Wa, 1u);
  k_edge_max_mask<<<GRID1, 256>>>(targets, sources, 1u);
  k_out          <<<(TOT/4 + 255) / 256, 256>>>(targets, sources, out);
}

// round 8
// speedup vs baseline: 1.0389x; 1.0389x over previous
#include <cuda_runtime.h>
#include <stdint.h>

// Problem shape (fixed by the dataset): B=1, N=100000, E=3200000, H=8, D=64
#define NN 100000
#define HH 8
#define DD 64
#define EE 3200000
#define TOT (EE*HH)          // 25,600,000 outputs
#define NWORDS (TOT/32)      // 800,000 packed mask words
#define WSPLIT 560000        // words produced in launch 1 (70%), rest launch 2

#define GRID1 1184           // 8 CTAs/SM * 148 SM
// Launch 1 roles: [0, D1) dots, [D1, GRID1) mask A
#define D1 736
#define MW1 ((GRID1 - D1) * 8)       // mask warps in launch 1
// Launch 2 roles: [0, D2) edge_max, [D2, GRID1) mask B
#define D2 736
#define MW2 ((GRID1 - D2) * 8)

// Scratch (static device arrays). 16B-aligned for vec I/O.
__device__ __align__(16) float    g_a_self[NN*HH];
__device__ __align__(16) float    g_a_adjc[NN*HH];
__device__ __align__(16) unsigned g_M[NN*HH];     // order-encoded per-(target,head) max
__device__ __align__(16) unsigned g_mask[NWORDS]; // packed keep bits

// ---------------------------------------------------------------------------
// Threefry-2x32 (20 rounds), key=(0,42), ctr=(0,j), JAX partitionable:
//   bits(j) = x0 ^ x1 ;  keep(j) = bit31 == 0.
// Adds forced onto the IMAD (fma) pipe via mad.lo.u32 with an opaque 'one' so
// the alu pipe carries only the mandatory SHF+LOP3 (40 warp-ops/eval).
// ---------------------------------------------------------------------------
__device__ __forceinline__ unsigned addm(unsigned a, unsigned one, unsigned b) {
  unsigned d;
  asm("mad.lo.u32 %0, %1, %2, %3;" : "=r"(d) : "r"(a), "r"(one), "r"(b));
  return d;
}
__device__ __forceinline__ unsigned tf_xor(unsigned j, unsigned one) {
  const unsigned K1  = 42u;
  const unsigned KS2 = 0x1BD11BDAu ^ 42u;
  unsigned x0 = 0u;                 // c0(=0) + ks0(=0)
  unsigned x1 = addm(j, one, K1);   // c1 + ks1
#define TF_R(r) { x0 = addm(x1, one, x0); x1 = __funnelshift_l(x1, x1, (r)); x1 ^= x0; }
  TF_R(13) TF_R(15) TF_R(26) TF_R(6)
  x0 = addm(one, K1, x0);   x1 = addm(one, KS2 + 1u, x1);
  TF_R(17) TF_R(29) TF_R(16) TF_R(24)
  x0 = addm(one, KS2, x0);  x1 = addm(one, 2u, x1);
  TF_R(13) TF_R(15) TF_R(26) TF_R(6)
  /* ks0 = 0 */             x1 = addm(one, K1 + 3u, x1);
  TF_R(17) TF_R(29) TF_R(16) TF_R(24)
  x0 = addm(one, K1, x0);   x1 = addm(one, KS2 + 4u, x1);
  TF_R(13) TF_R(15) TF_R(26) TF_R(6)
  x0 = addm(one, KS2, x0);  x1 = addm(one, 5u, x1);
#undef TF_R
  return x0 ^ x1;
}

// Mask words [w0, w1) over 'nw' warps, 2 words per iteration for ILP.
__device__ __forceinline__ void gen_mask(unsigned w0, unsigned w1, unsigned nw,
                                         unsigned mwarp, unsigned lane,
                                         unsigned one) {
  for (unsigned w = w0 + 2u*mwarp; w < w1; w += 2u*nw) {
    unsigned jA = w * 32u + lane;
    unsigned bitsA = tf_xor(jA, one);
    unsigned bitsB = (w + 1u < w1) ? tf_xor(jA + 32u, one) : 0u;
    unsigned wordA = __ballot_sync(0xFFFFFFFFu, (bitsA & 0x80000000u) == 0u);
    unsigned wordB = __ballot_sync(0xFFFFFFFFu, (bitsB & 0x80000000u) == 0u);
    if (lane == 0) {
      g_mask[w] = wordA;
      if (w + 1u < w1) g_mask[w + 1u] = wordB;
    }
  }
}

// Order-preserving float<->uint encoding for atomicMax
__device__ __forceinline__ unsigned enc_f(float f) {
  unsigned u = __float_as_uint(f);
  return (u & 0x80000000u) ? ~u : (u | 0x80000000u);
}
__device__ __forceinline__ float dec_f(unsigned k) {
  unsigned u = (k & 0x80000000u) ? (k ^ 0x80000000u) : ~k;
  return __uint_as_float(u);
}

// ---------------------------------------------------------------------------
// F1: CTA-role split.
//   bid <  D1 : dots (einsum 'nhd,dh->nh') + g_M zero-init (DRAM-bound)
//   bid >= D1 : mask words [0, WSPLIT)                      (ALU-bound)
// Classic bid->SM round-robin co-locates both roles on every SM -> pipes overlap.
// ---------------------------------------------------------------------------
#define DOTS_UN 4
__global__ void k_f1(const float* __restrict__ X,
                     const float* __restrict__ Ws,
                     const float* __restrict__ Wa,
                     unsigned one) {
  int l = threadIdx.x & 31;
  if (blockIdx.x >= D1) {
    unsigned mwarp = ((blockIdx.x - D1) * 256 + threadIdx.x) >> 5;
    gen_mask(0u, (unsigned)WSPLIT, (unsigned)MW1, mwarp, (unsigned)l, one);
    return;
  }
  int w = threadIdx.x >> 5;   // head
  float ws0 = Ws[(2*l    ) * HH + w];
  float ws1 = Ws[(2*l + 1) * HH + w];
  float wa0 = Wa[(2*l    ) * HH + w];
  float wa1 = Wa[(2*l + 1) * HH + w];

  for (int n0 = blockIdx.x * DOTS_UN; n0 < NN; n0 += D1 * DOTS_UN) {
    float2 x[DOTS_UN];
    int nv = (n0 + DOTS_UN <= NN) ? DOTS_UN : (NN - n0);
#pragma unroll
    for (int u = 0; u < DOTS_UN; u++)
      if (u < nv)
        x[u] = *reinterpret_cast<const float2*>(
            X + ((size_t)(n0 + u) * HH + w) * DD + 2*l);
    float ds[DOTS_UN], da[DOTS_UN];
#pragma unroll
    for (int u = 0; u < DOTS_UN; u++)
      if (u < nv) {
        ds[u] = x[u].x * ws0 + x[u].y * ws1;
        da[u] = x[u].x * wa0 + x[u].y * wa1;
      }
#pragma unroll
    for (int o = 16; o; o >>= 1)
#pragma unroll
      for (int u = 0; u < DOTS_UN; u++)
        if (u < nv) {
          ds[u] += __shfl_down_sync(0xFFFFFFFFu, ds[u], o);
          da[u] += __shfl_down_sync(0xFFFFFFFFu, da[u], o);
        }
    if (l == 0)
#pragma unroll
      for (int u = 0; u < DOTS_UN; u++)
        if (u < nv) {
          g_a_self[(n0 + u)*HH + w] = ds[u];
          g_a_adjc[(n0 + u)*HH + w] = da[u];
        }
    if (w == 0 && l < 8 * DOTS_UN) {       // fold g_M zero-init
      int u = l >> 3;
      if (u < nv) g_M[(n0 + u)*8 + (l & 7)] = 0u;
    }
  }
}

// ---------------------------------------------------------------------------
// F2: CTA-role split.
//   bid <  D2 : segment max (filtered atomics)  (L2-bound)
//   bid >= D2 : mask words [WSPLIT, NWORDS)     (ALU-bound)
// ---------------------------------------------------------------------------
__global__ void k_f2(const int* __restrict__ targets,
                     const int* __restrict__ sources,
                     unsigned one) {
  if (blockIdx.x >= D2) {
    unsigned mwarp = ((blockIdx.x - D2) * 256 + threadIdx.x) >> 5;
    gen_mask((unsigned)WSPLIT, (unsigned)NWORDS, (unsigned)MW2, mwarp,
             (unsigned)(threadIdx.x & 31), one);
    return;
  }
  for (int e = blockIdx.x * 256 + threadIdx.x; e < EE; e += D2 * 256) {
    int t = targets[e];
    int s = sources[e];
    const float4 a0 = *reinterpret_cast<const float4*>(g_a_adjc + s*8);
    const float4 a1 = *reinterpret_cast<const float4*>(g_a_adjc + s*8 + 4);
    const uint4  m0 = *reinterpret_cast<const uint4 *>(g_M + t*8);
    const uint4  m1 = *reinterpret_cast<const uint4 *>(g_M + t*8 + 4);
    unsigned v;
    v = enc_f(a0.x); if (v > m0.x) atomicMax(&g_M[t*8 + 0], v);
    v = enc_f(a0.y); if (v > m0.y) atomicMax(&g_M[t*8 + 1], v);
    v = enc_f(a0.z); if (v > m0.z) atomicMax(&g_M[t*8 + 2], v);
    v = enc_f(a0.w); if (v > m0.w) atomicMax(&g_M[t*8 + 3], v);
    v = enc_f(a1.x); if (v > m1.x) atomicMax(&g_M[t*8 + 4], v);
    v = enc_f(a1.y); if (v > m1.y) atomicMax(&g_M[t*8 + 5], v);
    v = enc_f(a1.z); if (v > m1.z) atomicMax(&g_M[t*8 + 6], v);
    v = enc_f(a1.w); if (v > m1.w) atomicMax(&g_M[t*8 + 7], v);
  }
}

// ---------------------------------------------------------------------------
// K3: out[j] = keepbit(j) ? 2*exp(e - m) : 0
//   e = leaky(a_self[t]+a_adjc[s]),  m = leaky(a_self[t]+max),  m2+eps == 1.0f
// 4 outputs per thread; mask from packed words -> memory-bound kernel.
// ---------------------------------------------------------------------------
__device__ __forceinline__ float edge_val(float a_s, float a_a, unsigned menc,
                                          unsigned keep) {
  float x  = a_s + a_a;
  float e  = (x  >= 0.0f) ? x  : 0.2f * x;
  float mx = a_s + dec_f(menc);
  float m  = (mx >= 0.0f) ? mx : 0.2f * mx;
  float v  = __expf(e - m) * 2.0f;
  return keep ? v : 0.0f;
}

__global__ void k_out(const int* __restrict__ targets,
                      const int* __restrict__ sources,
                      float* __restrict__ out) {
  unsigned tI = blockIdx.x * blockDim.x + threadIdx.x;  // 0 .. TOT/4-1
  if (tI >= (unsigned)(TOT/4)) return;
  unsigned j0 = 4u * tI;

  unsigned word = g_mask[j0 >> 5];
  unsigned b = word >> (j0 & 31u);

  int e = (int)(j0 >> 3);
  int h = (int)(j0 & 7u);        // 0 or 4
  int t = targets[e];
  int s = sources[e];
  float4 as = *reinterpret_cast<const float4*>(g_a_self + t*8 + h);
  float4 aa = *reinterpret_cast<const float4*>(g_a_adjc + s*8 + h);
  uint4  me = *reinterpret_cast<const uint4 *>(g_M      + t*8 + h);

  float4 o;
  o.x = edge_val(as.x, aa.x, me.x,  b        & 1u);
  o.y = edge_val(as.y, aa.y, me.y, (b >> 1u) & 1u);
  o.z = edge_val(as.z, aa.z, me.z, (b >> 2u) & 1u);
  o.w = edge_val(as.w, aa.w, me.w, (b >> 3u) & 1u);
  *reinterpret_cast<float4*>(out + j0) = o;
}

// ---------------------------------------------------------------------------
extern "C" void kernel_launch(void* const* d_in, const int* in_sizes, int n_in,
                              void* d_out, int out_size) {
  const float* X  = (const float*)d_in[0];
  const float* Ws = (const float*)d_in[1];
  const float* Wa = (const float*)d_in[2];
  // input order: X, Wself, Wadjc, [N scalar], targets, sources, degree
  int ti = (n_in >= 6 && in_sizes[3] == 1) ? 4 : 3;
  const int* targets = (const int*)d_in[ti];
  const int* sources = (const int*)d_in[ti + 1];
  float* out = (float*)d_out;

  k_f1 <<<GRID1, 256>>>(X, Ws, Wa, 1u);
  k_f2 <<<GRID1, 256>>>(targets, sources, 1u);
  k_out<<<(TOT/4 + 255) / 256, 256>>>(targets, sources, out);
}